// round 10
// baseline (speedup 1.0000x reference)
#include <cuda_runtime.h>

// Fixed problem shape
#define BGRAPH   512
#define MNODE    200
#define EPG      6400
#define DIMIN    128
#define KTOP     30
#define NTHREADS 256
#define NWARP    8
#define SRTCAP   7040                 // padded CSR capacity per graph (bytes)
#define SPW      (SRTCAP/4)           // CSR words per graph
#define SENTW    0xC8C8C8C8u          // 4x sentinel index 200 (zero row)

// packed fp32 helpers (Blackwell f32x2 pipe)
#define ADDX2(a, b) asm("add.rn.f32x2 %0, %1, %2;" : "=l"(a) : "l"(a), "l"(b))
#define FFMA2(d, a, b) asm("fma.rn.f32x2 %0, %1, %2, %0;" : "+l"(d) : "l"(a), "l"(b))

__device__ __forceinline__ unsigned long long dup2(float v) {
    unsigned long long r;
    asm("mov.b64 %0, {%1, %1};" : "=l"(r) : "f"(v));
    return r;
}
__device__ __forceinline__ float2 unpack2(unsigned long long v) {
    float2 r;
    asm("mov.b64 {%0, %1}, %2;" : "=f"(r.x), "=f"(r.y) : "l"(v));
    return r;
}

// ---------------- global scratch ----------------
__device__ float         g_h12[(size_t)BGRAPH * 2 * MNODE * 32];   // 26 MB
__device__ unsigned char g_srt[(size_t)BGRAPH * SRTCAP];           // 3.6 MB
__device__ int           g_start[(size_t)BGRAPH * 201];
__device__ float         g_dinv[(size_t)BGRAPH * MNODE];
__device__ float         g_yw[(size_t)BGRAPH * MNODE * 32];        // 13 MB

// =====================================================================
// Kernel A: per-graph degree + dinv + padded CSR build (to global)
// =====================================================================
__global__ __launch_bounds__(NTHREADS)
void build_kernel(const int* __restrict__ esrc, const int* __restrict__ edst)
{
    __shared__ int cnt[MNODE];
    __shared__ int start[MNODE + 1];
    const int g = blockIdx.x, tid = threadIdx.x;
    const int lane = tid & 31, wid = tid >> 5;
    const int nbase = g * MNODE, ebase = g * EPG;
    unsigned char* srtg = g_srt + (size_t)g * SRTCAP;

    for (int i = tid; i < MNODE; i += NTHREADS) cnt[i] = 0;
    __syncthreads();
    for (int e = tid; e < EPG; e += NTHREADS)
        atomicAdd(&cnt[edst[ebase + e] - nbase], 1);
    __syncthreads();

    for (int i = tid; i < MNODE; i += NTHREADS)
        g_dinv[g * MNODE + i] = rsqrtf((float)cnt[i] + 1.0f);

    if (wid == 0) {
        int base = lane * 7;
        int vals[7];
        int lsum = 0;
        #pragma unroll
        for (int j = 0; j < 7; ++j) {
            int idx = base + j;
            int v = (idx < MNODE) ? ((cnt[idx] + 3) & ~3) : 0;
            vals[j] = lsum; lsum += v;
        }
        int run = lsum;
        #pragma unroll
        for (int o = 1; o < 32; o <<= 1) {
            int t = __shfl_up_sync(0xffffffffu, run, o);
            if (lane >= o) run += t;
        }
        int excl = run - lsum;
        #pragma unroll
        for (int j = 0; j < 7; ++j) {
            int idx = base + j;
            if (idx < MNODE) start[idx] = excl + vals[j];
        }
        if (lane == 31) start[MNODE] = excl + lsum;
    }
    __syncthreads();

    for (int i = tid; i < MNODE + 1; i += NTHREADS)
        g_start[g * 201 + i] = start[i];
    for (int i = tid; i < MNODE; i += NTHREADS) cnt[i] = start[i];
    __syncthreads();

    for (int e = tid; e < EPG; e += NTHREADS) {
        int dl = edst[ebase + e] - nbase;
        int sl = esrc[ebase + e] - nbase;
        int slot = atomicAdd(&cnt[dl], 1);
        srtg[slot] = (unsigned char)sl;
    }
    __syncthreads();
    for (int i = tid; i < MNODE; i += NTHREADS) {
        int e0 = cnt[i], e1 = start[i + 1];
        for (int p = e0; p < e1; ++p) srtg[p] = 200;
    }
}

// =====================================================================
// Kernel B: g_yw = dinv * (x @ W1)   (per-graph, W1 staged in smem)
// =====================================================================
__device__ __forceinline__ void gemm_step_s(
    const float* __restrict__ wrow, float xa, float xb,
    unsigned long long &A01, unsigned long long &A23,
    unsigned long long &B01, unsigned long long &B23)
{
    ulonglong2 w2 = *(const ulonglong2*)wrow;
    unsigned long long xad = dup2(xa), xbd = dup2(xb);
    FFMA2(A01, w2.x, xad); FFMA2(A23, w2.y, xad);
    FFMA2(B01, w2.x, xbd); FFMA2(B23, w2.y, xbd);
}

__global__ __launch_bounds__(NTHREADS)
void gemm1_kernel(const float* __restrict__ x, const float* __restrict__ W1)
{
    __shared__ float W1s[DIMIN * 32];
    const int g = blockIdx.x, tid = threadIdx.x;
    const int nbase = g * MNODE;
    for (int i = tid; i < 1024; i += NTHREADS)
        ((float4*)W1s)[i] = __ldg((const float4*)W1 + i);
    __syncthreads();

    for (int t = tid; t < MNODE * 4; t += NTHREADS) {   // (rowpair, cg)
        int rp = t >> 3, cg = t & 7;
        int r0 = rp * 2;
        const float4* xr0 = (const float4*)(x + (size_t)(nbase + r0) * DIMIN);
        const float4* xr1 = xr0 + 32;
        const float*  wc  = W1s + 4 * cg;
        unsigned long long A01 = 0, A23 = 0, B01 = 0, B23 = 0;
        #pragma unroll 4
        for (int k4 = 0; k4 < 32; ++k4) {
            float4 xa = __ldg(xr0 + k4);
            float4 xb = __ldg(xr1 + k4);
            gemm_step_s(wc + (4*k4 + 0) * 32, xa.x, xb.x, A01, A23, B01, B23);
            gemm_step_s(wc + (4*k4 + 1) * 32, xa.y, xb.y, A01, A23, B01, B23);
            gemm_step_s(wc + (4*k4 + 2) * 32, xa.z, xb.z, A01, A23, B01, B23);
            gemm_step_s(wc + (4*k4 + 3) * 32, xa.w, xb.w, A01, A23, B01, B23);
        }
        float2 alo = unpack2(A01), ahi = unpack2(A23);
        float2 blo = unpack2(B01), bhi = unpack2(B23);
        float d0 = g_dinv[g * MNODE + r0], d1 = g_dinv[g * MNODE + r0 + 1];
        *(float4*)(g_yw + (size_t)(nbase + r0) * 32 + 4*cg) =
            make_float4(alo.x*d0, alo.y*d0, ahi.x*d0, ahi.y*d0);
        *(float4*)(g_yw + (size_t)(nbase + r0 + 1) * 32 + 4*cg) =
            make_float4(blo.x*d1, blo.y*d1, bhi.x*d1, bhi.y*d1);
    }
}

// =====================================================================
// Kernel C: fused layers (agg1..3, layer4, sortpool, convs, linears)
// =====================================================================
// SMEM: hcur[200*32] | yb[201*32] | dinv[200] | start[201]  = 52,944 B -> 4 CTAs/SM
#define SM_BYTES ((MNODE*32 + 201*32 + MNODE)*4 + 204*4)

#define AGG_BODY(w) { \
    ulonglong2 v0 = *(const ulonglong2*)(ybq + (((w) & 255u) << 7)); \
    ulonglong2 v1 = *(const ulonglong2*)(ybq + ((((w) >> 8) & 255u) << 7)); \
    ulonglong2 v2 = *(const ulonglong2*)(ybq + ((((w) >> 16) & 255u) << 7)); \
    ulonglong2 v3 = *(const ulonglong2*)(ybq + (((w) >> 24) << 7)); \
    ADDX2(a0x, v0.x); ADDX2(a0y, v0.y); \
    ADDX2(a1x, v1.x); ADDX2(a1y, v1.y); \
    ADDX2(a2x, v2.x); ADDX2(a2y, v2.y); \
    ADDX2(a3x, v3.x); ADDX2(a3y, v3.y); }

// 4-nodes-per-warp aggregation; group index words staged in 2 regs + shfl.
__device__ __forceinline__ void aggregate4s(
    const float* __restrict__ yb, const int* __restrict__ start,
    const unsigned int* __restrict__ spg, const char* __restrict__ ybq,
    const float* __restrict__ dinv, const float* __restrict__ bvec,
    float* __restrict__ hcur, float* __restrict__ gout,
    int wid, int lane, int quarter, int f8)
{
    float4 bb = __ldg((const float4*)bvec + f8);
    for (int ng = wid; ng < MNODE / 4; ng += NWARP) {
        int node  = 4 * ng + quarter;
        int wbase = start[4 * ng] >> 2;
        int nwrds = (start[4 * ng + 4] >> 2) - wbase;
        int off   = (start[node] >> 2) - wbase;
        int nq    = (start[node + 1] >> 2) - (start[node] >> 2);
        int maxq  = __reduce_max_sync(0xffffffffu, nq);
        unsigned long long a0x=0,a0y=0,a1x=0,a1y=0,a2x=0,a2y=0,a3x=0,a3y=0;
        if (nwrds <= 64) {
            unsigned r0 = __ldg(spg + min(wbase + lane, SPW - 1));
            unsigned r1 = __ldg(spg + min(wbase + 32 + lane, SPW - 1));
            for (int q = 0; q < maxq; ++q) {
                int idx = off + q;
                unsigned s0 = __shfl_sync(0xffffffffu, r0, idx & 31);
                unsigned s1 = __shfl_sync(0xffffffffu, r1, idx & 31);
                unsigned w = (q < nq) ? ((idx < 32) ? s0 : s1) : SENTW;
                AGG_BODY(w);
            }
        } else {  // rare fallback (sum-degree of group > 256 edges)
            for (int q = 0; q < maxq; ++q) {
                unsigned w = (q < nq) ? __ldg(spg + wbase + off + q) : SENTW;
                AGG_BODY(w);
            }
        }
        ADDX2(a0x, a1x); ADDX2(a2x, a3x); ADDX2(a0x, a2x);
        ADDX2(a0y, a1y); ADDX2(a2y, a3y); ADDX2(a0y, a2y);
        float2 sxy = unpack2(a0x), szw = unpack2(a0y);
        float4 self = *(const float4*)(yb + node * 32 + 4 * f8);
        float d = dinv[node];
        float4 hv;
        hv.x = tanhf(d * (sxy.x + self.x) + bb.x);
        hv.y = tanhf(d * (sxy.y + self.y) + bb.y);
        hv.z = tanhf(d * (szw.x + self.z) + bb.z);
        hv.w = tanhf(d * (szw.y + self.w) + bb.w);
        *(float4*)(hcur + node * 32 + 4 * f8) = hv;
        if (gout) *(float4*)(gout + node * 32 + 4 * f8) = hv;
    }
}

// GEMM k-step with weights from global (__ldg, broadcast-dedup)
__device__ __forceinline__ void gemm_step_g(
    const float* __restrict__ wrow, float xa, float xb,
    unsigned long long &A01, unsigned long long &A23,
    unsigned long long &B01, unsigned long long &B23)
{
    ulonglong2 w2 = __ldg((const ulonglong2*)wrow);
    unsigned long long xad = dup2(xa), xbd = dup2(xb);
    FFMA2(A01, w2.x, xad); FFMA2(A23, w2.y, xad);
    FFMA2(B01, w2.x, xbd); FFMA2(B23, w2.y, xbd);
}

__global__ __launch_bounds__(NTHREADS, 4)
void dgcnn_fused_kernel(const float* __restrict__ b1,
                        const float* __restrict__ W2, const float* __restrict__ b2,
                        const float* __restrict__ W3, const float* __restrict__ b3,
                        const float* __restrict__ W4, const float* __restrict__ b4,
                        const float* __restrict__ cW1, const float* __restrict__ cb1,
                        const float* __restrict__ cW2, const float* __restrict__ cb2,
                        const float* __restrict__ lW1, const float* __restrict__ lb1,
                        const float* __restrict__ lW2, const float* __restrict__ lb2,
                        float* __restrict__ out)
{
    extern __shared__ char smem[];
    float* hcur = (float*)smem;                 // [200][32]
    float* yb   = hcur + MNODE*32;              // [201][32] (row 200 = zero sentinel)
    float* dinv = yb + 201*32;                  // [200]
    int*   start = (int*)(dinv + MNODE);        // [201]

    // yb-region overlays (phase-disjoint, after layer-4 GEMM part):
    float* y4   = yb;                           // [201] (y4[200]=0)
    float* h4   = yb + 256;                     // [200]
    int*   ordx = (int*)(yb + 512);             // [30]
    float* h1t  = yb + 544;                     // [30*32]
    float* h2t  = yb + 1504;                    // [30*32]
    float* h3t  = yb + 2464;                    // [30*32]
    float* c1   = yb + 3424;                    // [16*30]
    float* pp   = yb + 3904;                    // [16*15]
    float* c2   = yb + 4144;                    // [32*11]
    float* hl   = yb + 4496;                    // [128]
    float* hl2  = yb + 4624;                    // [128]

    const int g       = blockIdx.x;
    const int tid     = threadIdx.x;
    const int lane    = tid & 31;
    const int wid     = tid >> 5;
    const int quarter = lane >> 3;
    const int f8      = lane & 7;
    const int nbase   = g * MNODE;
    const unsigned int* spg = (const unsigned int*)(g_srt + (size_t)g * SRTCAP);
    const char* ybq = (const char*)yb + (f8 << 4);

    // ---------------- stage dinv, start, yb(=dinv*xW1) ----------------
    for (int i = tid; i < MNODE; i += NTHREADS) dinv[i] = g_dinv[g * MNODE + i];
    for (int i = tid; i < MNODE + 1; i += NTHREADS) start[i] = g_start[g * 201 + i];
    for (int i = tid; i < MNODE * 8; i += NTHREADS)
        ((float4*)yb)[i] = __ldg((const float4*)(g_yw + (size_t)nbase * 32) + i);
    if (tid < 32) yb[200 * 32 + tid] = 0.f;     // sentinel row (stays zero)
    __syncthreads();

    // ---------------- layer 1 aggregation -> hcur = h1 ----------------
    aggregate4s(yb, start, spg, ybq, dinv, b1, hcur,
                g_h12 + ((size_t)g * 2 + 0) * MNODE * 32, wid, lane, quarter, f8);
    __syncthreads();

    // ---------------- layers 2, 3 ----------------
    #pragma unroll 1
    for (int L = 0; L < 2; ++L) {
        const float* W = L ? W3 : W2;
        const float* b = L ? b3 : b2;
        for (int t = tid; t < MNODE * 4; t += NTHREADS) {
            int rp = t >> 3, cg = t & 7;
            int r0 = rp * 2;
            const float* h0r = hcur + r0 * 32;
            const float* h1r = h0r + 32;
            const float* wc  = W + 4 * cg;
            unsigned long long A01 = 0, A23 = 0, B01 = 0, B23 = 0;
            #pragma unroll
            for (int k4 = 0; k4 < 8; ++k4) {
                float4 ha = *(const float4*)(h0r + 4*k4);
                float4 hb = *(const float4*)(h1r + 4*k4);
                gemm_step_g(wc + (4*k4 + 0) * 32, ha.x, hb.x, A01, A23, B01, B23);
                gemm_step_g(wc + (4*k4 + 1) * 32, ha.y, hb.y, A01, A23, B01, B23);
                gemm_step_g(wc + (4*k4 + 2) * 32, ha.z, hb.z, A01, A23, B01, B23);
                gemm_step_g(wc + (4*k4 + 3) * 32, ha.w, hb.w, A01, A23, B01, B23);
            }
            float2 alo = unpack2(A01), ahi = unpack2(A23);
            float2 blo = unpack2(B01), bhi = unpack2(B23);
            float d0 = dinv[r0], d1 = dinv[r0 + 1];
            *(float4*)(yb + r0 * 32 + 4*cg)       = make_float4(alo.x*d0, alo.y*d0, ahi.x*d0, ahi.y*d0);
            *(float4*)(yb + (r0 + 1) * 32 + 4*cg) = make_float4(blo.x*d1, blo.y*d1, bhi.x*d1, bhi.y*d1);
        }
        __syncthreads();
        aggregate4s(yb, start, spg, ybq, dinv, b, hcur,
                    (L == 0) ? (g_h12 + ((size_t)g * 2 + 1) * MNODE * 32) : (float*)0,
                    wid, lane, quarter, f8);
        __syncthreads();
    }

    // ---------------- layer 4 (Fout = 1) ----------------
    {
        float w4v = __ldg(W4 + lane);
        for (int node = wid; node < MNODE; node += NWARP) {
            float v = hcur[node * 32 + lane] * w4v;
            #pragma unroll
            for (int o = 16; o; o >>= 1) v += __shfl_xor_sync(0xffffffffu, v, o);
            if (lane == 0) y4[node] = dinv[node] * v;
        }
        if (tid == 0) y4[200] = 0.f;
    }
    __syncthreads();
    {
        float b4v = __ldg(b4);
        for (int node = tid; node < MNODE; node += NTHREADS) {
            int q0 = start[node] >> 2, q1 = start[node + 1] >> 2;
            float acc = 0.f;
            for (int q = q0; q < q1; ++q) {
                unsigned int w = __ldg(spg + q);
                acc += y4[w & 255u] + y4[(w >> 8) & 255u]
                     + y4[(w >> 16) & 255u] + y4[w >> 24];
            }
            h4[node] = tanhf(dinv[node] * (acc + y4[node]) + b4v);
        }
    }
    __syncthreads();

    // ---------------- SortPool: top-30 by h4, stable desc ----------------
    for (int i = tid; i < MNODE; i += NTHREADS) {
        float v = h4[i];
        int rank = 0;
        for (int j = 0; j < MNODE; ++j) {
            float vj = h4[j];
            rank += (vj > v) || (vj == v && j < i);
        }
        if (rank < KTOP) ordx[rank] = i;
    }
    __syncthreads();

    // gather h1,h2 (global) and h3 (smem) rows of top-K nodes
    for (int i = tid; i < KTOP * 32 * 3; i += NTHREADS) {
        int L = i / (KTOP * 32);
        int idx = i - L * KTOP * 32;
        int slot = idx >> 5, f = idx & 31;
        int node = ordx[slot];
        float v;
        if (L < 2) v = g_h12[((size_t)g * 2 + L) * MNODE * 32 + node * 32 + f];
        else       v = hcur[node * 32 + f];
        (L == 0 ? h1t : (L == 1 ? h2t : h3t))[idx] = v;
    }
    __syncthreads();

    // ---------------- Conv1: 1->16, taps 97, stride 97 ----------------
    for (int it = tid; it < 16 * KTOP; it += NTHREADS) {
        int o = it / KTOP, k = it % KTOP;
        const float* w  = cW1 + o * 97;
        const float* a1 = h1t + k * 32;
        const float* a2 = h2t + k * 32;
        const float* a3 = h3t + k * 32;
        float s = __ldg(cb1 + o);
        #pragma unroll 8
        for (int f = 0; f < 32; ++f) s += a1[f] * __ldg(w + f);
        #pragma unroll 8
        for (int f = 0; f < 32; ++f) s += a2[f] * __ldg(w + 32 + f);
        #pragma unroll 8
        for (int f = 0; f < 32; ++f) s += a3[f] * __ldg(w + 64 + f);
        s += h4[ordx[k]] * __ldg(w + 96);
        c1[o * KTOP + k] = fmaxf(s, 0.f);
    }
    __syncthreads();

    // ---------------- MaxPool1d(2,2) ----------------
    for (int it = tid; it < 16 * 15; it += NTHREADS) {
        int o = it / 15, t = it % 15;
        pp[it] = fmaxf(c1[o * KTOP + 2 * t], c1[o * KTOP + 2 * t + 1]);
    }
    __syncthreads();

    // ---------------- Conv2: 16->32, k=5 -> [32][11] ----------------
    for (int it = tid; it < 32 * 11; it += NTHREADS) {
        int o = it / 11, t = it % 11;
        const float* w = cW2 + o * 80;
        float s = __ldg(cb2 + o);
        #pragma unroll
        for (int i = 0; i < 16; ++i)
            #pragma unroll
            for (int j = 0; j < 5; ++j)
                s += __ldg(w + i * 5 + j) * pp[i * 15 + t + j];
        c2[it] = fmaxf(s, 0.f);
    }
    __syncthreads();

    // ---------------- Linear 352 -> 128 (split-2) ----------------
    {
        int h = tid & 127, hhalf = tid >> 7;
        const float* base = lW1 + h;
        float s = hhalf ? 0.f : __ldg(lb1 + h);
        int i0 = hhalf * 176;
        #pragma unroll 8
        for (int i = i0; i < i0 + 176; ++i)
            s += c2[i] * __ldg(base + i * 128);
        (hhalf ? hl2 : hl)[h] = s;
    }
    __syncthreads();

    // ---------------- Linear 128 -> 1, sigmoid ----------------
    if (wid == 0) {
        float v = 0.f;
        #pragma unroll
        for (int i = lane; i < 128; i += 32) {
            float hv = fmaxf(hl[i] + hl2[i], 0.f);
            v += hv * __ldg(lW2 + i);
        }
        #pragma unroll
        for (int o = 16; o; o >>= 1) v += __shfl_xor_sync(0xffffffffu, v, o);
        if (lane == 0)
            out[g] = 1.0f / (1.0f + expf(-(v + __ldg(lb2))));
    }
}

extern "C" void kernel_launch(void* const* d_in, const int* in_sizes, int n_in,
                              void* d_out, int out_size)
{
    const float* x    = (const float*)d_in[0];
    const int*   ei   = (const int*)  d_in[1];
    const float* W1   = (const float*)d_in[3];
    const float* b1   = (const float*)d_in[4];
    const float* W2   = (const float*)d_in[5];
    const float* b2   = (const float*)d_in[6];
    const float* W3   = (const float*)d_in[7];
    const float* b3   = (const float*)d_in[8];
    const float* W4   = (const float*)d_in[9];
    const float* b4   = (const float*)d_in[10];
    const float* cW1  = (const float*)d_in[11];
    const float* cb1  = (const float*)d_in[12];
    const float* cW2  = (const float*)d_in[13];
    const float* cb2  = (const float*)d_in[14];
    const float* lW1  = (const float*)d_in[15];
    const float* lb1  = (const float*)d_in[16];
    const float* lW2  = (const float*)d_in[17];
    const float* lb2  = (const float*)d_in[18];

    const int E = in_sizes[1] / 2;
    const int* esrc = ei;
    const int* edst = ei + E;

    build_kernel<<<BGRAPH, NTHREADS>>>(esrc, edst);
    gemm1_kernel<<<BGRAPH, NTHREADS>>>(x, W1);

    cudaFuncSetAttribute(dgcnn_fused_kernel,
                         cudaFuncAttributeMaxDynamicSharedMemorySize, SM_BYTES);
    dgcnn_fused_kernel<<<BGRAPH, NTHREADS, SM_BYTES>>>(
        b1, W2, b2, W3, b3, W4, b4,
        cW1, cb1, cW2, cb2, lW1, lb1, lW2, lb2,
        (float*)d_out);
}

// round 11
// speedup vs baseline: 1.3153x; 1.3153x over previous
#include <cuda_runtime.h>

// Fixed problem shape
#define BGRAPH   512
#define MNODE    200
#define EPG      6400
#define DIMIN    128
#define KTOP     30
#define NTHREADS 256
#define NWARP    8
#define SH       36          // hcur row stride (float4-aligned, conflict-free)
#define SRTCAP   7040        // padded CSR capacity
#define SENTW    0xC8C8C8C8u // 4x sentinel index 200 (zero row)

// packed fp32 helpers (Blackwell f32x2 pipe)
#define ADDX2(a, b) asm("add.rn.f32x2 %0, %1, %2;" : "=l"(a) : "l"(a), "l"(b))
#define FFMA2(d, a, b) asm("fma.rn.f32x2 %0, %1, %2, %0;" : "+l"(d) : "l"(a), "l"(b))

__device__ __forceinline__ unsigned long long dup2(float v) {
    unsigned long long r;
    asm("mov.b64 %0, {%1, %1};" : "=l"(r) : "f"(v));
    return r;
}
__device__ __forceinline__ float2 unpack2(unsigned long long v) {
    float2 r;
    asm("mov.b64 {%0, %1}, %2;" : "=f"(r.x), "=f"(r.y) : "l"(v));
    return r;
}
// single-instruction MUFU tanh (max abs err ~1.4e-5; inside 1e-3 budget)
__device__ __forceinline__ float tanh_fast(float x) {
    float y;
    asm("tanh.approx.f32 %0, %1;" : "=f"(y) : "f"(x));
    return y;
}

// Global staging for h1,h2 rows (re-gathered only for top-K at the end). 26 MB.
__device__ float g_h12[(size_t)BGRAPH * 2 * MNODE * 32];

// SMEM: hcur[200*36] | yb[201*32] | Ws[2048] | dinv[200] | start[201]i | srt u8[7040]
#define SM_BYTES (28800 + 25728 + 8192 + 800 + 804 + SRTCAP)   // 71364 -> 3 CTAs/SM

// 4-nodes-per-warp aggregation with packed adds + index prefetch.
// lane = 8*quarter + f8 ; lane owns feats [4*f8, 4*f8+4) of node 4*ng+quarter.
__device__ __forceinline__ void aggregate4(
    const float* __restrict__ yb, const int* __restrict__ start,
    const unsigned int* __restrict__ sp, const char* __restrict__ ybq,
    const float* __restrict__ dinv, const float* __restrict__ bvec,
    float* __restrict__ hcur, float* __restrict__ gout,
    int wid, int quarter, int f8)
{
    float4 bb = __ldg((const float4*)bvec + f8);
    for (int ng = wid; ng < MNODE / 4; ng += NWARP) {
        int node = 4 * ng + quarter;
        int q0 = start[node] >> 2;
        int nq = (start[node + 1] >> 2) - q0;
        int maxq = __reduce_max_sync(0xffffffffu, nq);
        unsigned long long a0x=0,a0y=0,a1x=0,a1y=0,a2x=0,a2y=0,a3x=0,a3y=0;
        unsigned int w = (nq > 0) ? sp[q0] : SENTW;
        for (int q = 0; q < maxq; ++q) {
            unsigned int wn = (q + 1 < nq) ? sp[q0 + q + 1] : SENTW;
            ulonglong2 v0 = *(const ulonglong2*)(ybq + ((w & 255u) << 7));
            ulonglong2 v1 = *(const ulonglong2*)(ybq + (((w >> 8) & 255u) << 7));
            ulonglong2 v2 = *(const ulonglong2*)(ybq + (((w >> 16) & 255u) << 7));
            ulonglong2 v3 = *(const ulonglong2*)(ybq + ((w >> 24) << 7));
            ADDX2(a0x, v0.x); ADDX2(a0y, v0.y);
            ADDX2(a1x, v1.x); ADDX2(a1y, v1.y);
            ADDX2(a2x, v2.x); ADDX2(a2y, v2.y);
            ADDX2(a3x, v3.x); ADDX2(a3y, v3.y);
            w = wn;
        }
        ADDX2(a0x, a1x); ADDX2(a2x, a3x); ADDX2(a0x, a2x);
        ADDX2(a0y, a1y); ADDX2(a2y, a3y); ADDX2(a0y, a2y);
        float2 sxy = unpack2(a0x), szw = unpack2(a0y);
        float4 self = *(const float4*)(yb + node * 32 + 4 * f8);
        float d = dinv[node];
        float4 hv;
        hv.x = tanh_fast(d * (sxy.x + self.x) + bb.x);
        hv.y = tanh_fast(d * (sxy.y + self.y) + bb.y);
        hv.z = tanh_fast(d * (szw.x + self.z) + bb.z);
        hv.w = tanh_fast(d * (szw.y + self.w) + bb.w);
        *(float4*)(hcur + node * SH + 4 * f8) = hv;
        if (gout) *(float4*)(gout + node * 32 + 4 * f8) = hv;
    }
}

// one packed GEMM k-step: 2 rows x 4 cols against one weight row (float4 in smem)
__device__ __forceinline__ void gemm_step(
    const float* __restrict__ wrow, float xa, float xb,
    unsigned long long &A01, unsigned long long &A23,
    unsigned long long &B01, unsigned long long &B23)
{
    ulonglong2 w2 = *(const ulonglong2*)wrow;
    unsigned long long xad = dup2(xa), xbd = dup2(xb);
    FFMA2(A01, w2.x, xad); FFMA2(A23, w2.y, xad);
    FFMA2(B01, w2.x, xbd); FFMA2(B23, w2.y, xbd);
}

__global__ __launch_bounds__(NTHREADS, 3)
void dgcnn_fused_kernel(const float* __restrict__ x,
                        const int*   __restrict__ esrc,
                        const int*   __restrict__ edst,
                        const float* __restrict__ W1, const float* __restrict__ b1,
                        const float* __restrict__ W2, const float* __restrict__ b2,
                        const float* __restrict__ W3, const float* __restrict__ b3,
                        const float* __restrict__ W4, const float* __restrict__ b4,
                        const float* __restrict__ cW1, const float* __restrict__ cb1,
                        const float* __restrict__ cW2, const float* __restrict__ cb2,
                        const float* __restrict__ lW1, const float* __restrict__ lb1,
                        const float* __restrict__ lW2, const float* __restrict__ lb2,
                        float* __restrict__ out)
{
    extern __shared__ char smem[];
    float* hcur = (float*)smem;                 // [200][36]; W1s overlay in layer-1 GEMM
    float* yb   = hcur + MNODE*SH;              // [201][32] (row 200 = zero sentinel)
    float* Ws   = yb + 201*32;                  // [2048]: W2 then W3
    float* dinv = Ws + 2048;                    // [200]
    int*   start = (int*)(dinv + MNODE);        // [201] padded CSR offsets
    unsigned char* srt = (unsigned char*)(start + 201); // [7040]

    // yb-region overlays (phase-disjoint):
    int*   cnt  = (int*)yb;                     // build phase [200]
    float* y4   = yb;                           // [201] (y4[200]=0 sentinel)
    float* h4   = yb + 256;                     // [200]
    int*   ordx = (int*)(yb + 512);             // [30]
    float* h1t  = yb + 544;                     // [30*32]
    float* h2t  = yb + 1504;                    // [30*32]
    float* c1   = yb + 2464;                    // [16*30]
    float* pp   = yb + 2944;                    // [16*15]
    float* c2   = yb + 3184;                    // [32*11]
    float* hl   = yb + 3536;                    // [128]
    float* hl2  = yb + 3664;                    // [128]

    const int g       = blockIdx.x;
    const int tid     = threadIdx.x;
    const int lane    = tid & 31;
    const int wid     = tid >> 5;
    const int quarter = lane >> 3;              // node-in-group
    const int f8      = lane & 7;               // feature-quad id
    const int nbase   = g * MNODE;
    const int4* edst4 = (const int4*)(edst + g * EPG);
    const int4* esrc4 = (const int4*)(esrc + g * EPG);

    // ---------------- stage W2,W3 into smem; zero counts ----------------
    for (int i = tid; i < MNODE; i += NTHREADS) cnt[i] = 0;
    {
        float4* Ws4 = (float4*)Ws;
        for (int i = tid; i < 256; i += NTHREADS) {
            Ws4[i]       = __ldg((const float4*)W2 + i);
            Ws4[i + 256] = __ldg((const float4*)W3 + i);
        }
    }
    __syncthreads();

    // ---------------- degree counts (int4-vectorized edge loads) ----------------
    for (int e4 = tid; e4 < EPG / 4; e4 += NTHREADS) {
        int4 d4 = __ldg(edst4 + e4);
        atomicAdd(&cnt[d4.x - nbase], 1);
        atomicAdd(&cnt[d4.y - nbase], 1);
        atomicAdd(&cnt[d4.z - nbase], 1);
        atomicAdd(&cnt[d4.w - nbase], 1);
    }
    __syncthreads();

    for (int i = tid; i < MNODE; i += NTHREADS)
        dinv[i] = rsqrtf((float)cnt[i] + 1.0f);

    // ---------------- exclusive prefix over PADDED counts (warp 0) ----------------
    if (wid == 0) {
        int base = lane * 7;
        int vals[7];
        int lsum = 0;
        #pragma unroll
        for (int j = 0; j < 7; ++j) {
            int idx = base + j;
            int v = (idx < MNODE) ? ((cnt[idx] + 3) & ~3) : 0;
            vals[j] = lsum; lsum += v;
        }
        int run = lsum;
        #pragma unroll
        for (int o = 1; o < 32; o <<= 1) {
            int t = __shfl_up_sync(0xffffffffu, run, o);
            if (lane >= o) run += t;
        }
        int excl = run - lsum;
        #pragma unroll
        for (int j = 0; j < 7; ++j) {
            int idx = base + j;
            if (idx < MNODE) start[idx] = excl + vals[j];
        }
        if (lane == 31) start[MNODE] = excl + lsum;
    }
    __syncthreads();

    for (int i = tid; i < MNODE; i += NTHREADS) cnt[i] = start[i];
    __syncthreads();

    // ---------------- CSR scatter (int4-vectorized loads, u8 lists) ----------------
    for (int e4 = tid; e4 < EPG / 4; e4 += NTHREADS) {
        int4 d4 = __ldg(edst4 + e4);
        int4 s4 = __ldg(esrc4 + e4);
        srt[atomicAdd(&cnt[d4.x - nbase], 1)] = (unsigned char)(s4.x - nbase);
        srt[atomicAdd(&cnt[d4.y - nbase], 1)] = (unsigned char)(s4.y - nbase);
        srt[atomicAdd(&cnt[d4.z - nbase], 1)] = (unsigned char)(s4.z - nbase);
        srt[atomicAdd(&cnt[d4.w - nbase], 1)] = (unsigned char)(s4.w - nbase);
    }
    __syncthreads();
    for (int i = tid; i < MNODE; i += NTHREADS) {
        int e0 = cnt[i], e1 = start[i + 1];
        for (int p = e0; p < e1; ++p) srt[p] = 200;   // sentinel -> zero row
    }
    if (tid < 32) yb[200 * 32 + tid] = 0.f;
    __syncthreads();

    const unsigned int* sp = (const unsigned int*)srt;
    const char* ybq = (const char*)yb + (f8 << 4);    // per-lane float4 base

    // ============== Layer 1: yb = dinv * (x @ W1)  (packed FFMA2, W1 smem) ======
    {
        float4* W1s4 = (float4*)hcur;           // hcur dead until h1 write
        for (int i = tid; i < 1024; i += NTHREADS)
            W1s4[i] = __ldg((const float4*)W1 + i);
    }
    __syncthreads();
    for (int t = tid; t < MNODE * 4; t += NTHREADS) {   // 800 items: (rowpair, cg)
        int rp = t >> 3, cg = t & 7;
        int r0 = rp * 2;
        const float4* xr0 = (const float4*)(x + (size_t)(nbase + r0) * DIMIN);
        const float4* xr1 = xr0 + 32;
        const float*  wc  = hcur + 4 * cg;
        unsigned long long A01 = 0, A23 = 0, B01 = 0, B23 = 0;
        #pragma unroll 4
        for (int k4 = 0; k4 < 32; ++k4) {
            float4 xa = __ldg(xr0 + k4);
            float4 xb = __ldg(xr1 + k4);
            gemm_step(wc + (4*k4 + 0) * 32, xa.x, xb.x, A01, A23, B01, B23);
            gemm_step(wc + (4*k4 + 1) * 32, xa.y, xb.y, A01, A23, B01, B23);
            gemm_step(wc + (4*k4 + 2) * 32, xa.z, xb.z, A01, A23, B01, B23);
            gemm_step(wc + (4*k4 + 3) * 32, xa.w, xb.w, A01, A23, B01, B23);
        }
        float2 alo = unpack2(A01), ahi = unpack2(A23);
        float2 blo = unpack2(B01), bhi = unpack2(B23);
        float d0 = dinv[r0], d1 = dinv[r0 + 1];
        *(float4*)(yb + r0 * 32 + 4*cg)       = make_float4(alo.x*d0, alo.y*d0, ahi.x*d0, ahi.y*d0);
        *(float4*)(yb + (r0 + 1) * 32 + 4*cg) = make_float4(blo.x*d1, blo.y*d1, bhi.x*d1, bhi.y*d1);
    }
    __syncthreads();

    // aggregation -> hcur = h1, stage to global
    aggregate4(yb, start, sp, ybq, dinv, b1, hcur,
               g_h12 + ((size_t)g * 2 + 0) * MNODE * 32, wid, quarter, f8);
    __syncthreads();

    // ============== Layers 2 and 3 (packed FFMA2, W from smem) ==============
    #pragma unroll 1
    for (int L = 0; L < 2; ++L) {
        const float* Wl = Ws + L * 1024;
        const float* b  = L ? b3 : b2;
        for (int t = tid; t < MNODE * 4; t += NTHREADS) {
            int rp = t >> 3, cg = t & 7;
            int r0 = rp * 2;
            const float* h0r = hcur + r0 * SH;
            const float* h1r = h0r + SH;
            const float* wc  = Wl + 4 * cg;
            unsigned long long A01 = 0, A23 = 0, B01 = 0, B23 = 0;
            #pragma unroll
            for (int k4 = 0; k4 < 8; ++k4) {
                float4 ha = *(const float4*)(h0r + 4*k4);
                float4 hb = *(const float4*)(h1r + 4*k4);
                gemm_step(wc + (4*k4 + 0) * 32, ha.x, hb.x, A01, A23, B01, B23);
                gemm_step(wc + (4*k4 + 1) * 32, ha.y, hb.y, A01, A23, B01, B23);
                gemm_step(wc + (4*k4 + 2) * 32, ha.z, hb.z, A01, A23, B01, B23);
                gemm_step(wc + (4*k4 + 3) * 32, ha.w, hb.w, A01, A23, B01, B23);
            }
            float2 alo = unpack2(A01), ahi = unpack2(A23);
            float2 blo = unpack2(B01), bhi = unpack2(B23);
            float d0 = dinv[r0], d1 = dinv[r0 + 1];
            *(float4*)(yb + r0 * 32 + 4*cg)       = make_float4(alo.x*d0, alo.y*d0, ahi.x*d0, ahi.y*d0);
            *(float4*)(yb + (r0 + 1) * 32 + 4*cg) = make_float4(blo.x*d1, blo.y*d1, bhi.x*d1, bhi.y*d1);
        }
        __syncthreads();
        aggregate4(yb, start, sp, ybq, dinv, b, hcur,
                   (L == 0) ? (g_h12 + ((size_t)g * 2 + 1) * MNODE * 32) : (float*)0,
                   wid, quarter, f8);
        __syncthreads();
    }

    // ============== Layer 4 (Fout = 1) ==============
    {
        float w4v = __ldg(W4 + lane);
        for (int node = wid; node < MNODE; node += NWARP) {
            float v = hcur[node * SH + lane] * w4v;
            #pragma unroll
            for (int o = 16; o; o >>= 1) v += __shfl_xor_sync(0xffffffffu, v, o);
            if (lane == 0) y4[node] = dinv[node] * v;
        }
        if (tid == 0) y4[200] = 0.f;            // sentinel
    }
    __syncthreads();
    {
        float b4v = __ldg(b4);
        for (int node = tid; node < MNODE; node += NTHREADS) {
            int q0 = start[node] >> 2, q1 = start[node + 1] >> 2;
            float acc = 0.f;
            for (int q = q0; q < q1; ++q) {
                unsigned int w = sp[q];
                acc += y4[w & 255u] + y4[(w >> 8) & 255u]
                     + y4[(w >> 16) & 255u] + y4[w >> 24];
            }
            h4[node] = tanh_fast(dinv[node] * (acc + y4[node]) + b4v);
        }
    }
    __syncthreads();

    // ============== SortPool: top-30 by h4, stable desc ==============
    for (int i = tid; i < MNODE; i += NTHREADS) {
        float v = h4[i];
        int rank = 0;
        for (int j = 0; j < MNODE; ++j) {
            float vj = h4[j];
            rank += (vj > v) || (vj == v && j < i);
        }
        if (rank < KTOP) ordx[rank] = i;
    }
    __syncthreads();

    // gather h1,h2 rows of top-K nodes from global staging
    for (int i = tid; i < KTOP * 32 * 2; i += NTHREADS) {
        int L = (i >= KTOP * 32);
        int idx = i - L * KTOP * 32;
        int slot = idx >> 5, f = idx & 31;
        int node = ordx[slot];
        float v = g_h12[((size_t)g * 2 + L) * MNODE * 32 + node * 32 + f];
        (L ? h2t : h1t)[idx] = v;
    }
    __syncthreads();

    // ============== Conv1: 1->16, taps 97, stride 97 ==============
    for (int it = tid; it < 16 * KTOP; it += NTHREADS) {
        int o = it / KTOP, k = it % KTOP;
        int node = ordx[k];
        const float* w  = cW1 + o * 97;
        const float* a1 = h1t + k * 32;
        const float* a2 = h2t + k * 32;
        const float* a3 = hcur + node * SH;
        float s = __ldg(cb1 + o);
        #pragma unroll 8
        for (int f = 0; f < 32; ++f) s += a1[f] * __ldg(w + f);
        #pragma unroll 8
        for (int f = 0; f < 32; ++f) s += a2[f] * __ldg(w + 32 + f);
        #pragma unroll 8
        for (int f = 0; f < 32; ++f) s += a3[f] * __ldg(w + 64 + f);
        s += h4[node] * __ldg(w + 96);
        c1[o * KTOP + k] = fmaxf(s, 0.f);
    }
    __syncthreads();

    // ============== MaxPool1d(2,2) ==============
    for (int it = tid; it < 16 * 15; it += NTHREADS) {
        int o = it / 15, t = it % 15;
        pp[it] = fmaxf(c1[o * KTOP + 2 * t], c1[o * KTOP + 2 * t + 1]);
    }
    __syncthreads();

    // ============== Conv2: 16->32, k=5 -> [32][11] ==============
    for (int it = tid; it < 32 * 11; it += NTHREADS) {
        int o = it / 11, t = it % 11;
        const float* w = cW2 + o * 80;
        float s = __ldg(cb2 + o);
        #pragma unroll
        for (int i = 0; i < 16; ++i)
            #pragma unroll
            for (int j = 0; j < 5; ++j)
                s += __ldg(w + i * 5 + j) * pp[i * 15 + t + j];
        c2[it] = fmaxf(s, 0.f);
    }
    __syncthreads();

    // ============== Linear 352 -> 128 (split-2) ==============
    {
        int h = tid & 127, hhalf = tid >> 7;
        const float* base = lW1 + h;
        float s = hhalf ? 0.f : __ldg(lb1 + h);
        int i0 = hhalf * 176;
        #pragma unroll 8
        for (int i = i0; i < i0 + 176; ++i)
            s += c2[i] * __ldg(base + i * 128);
        (hhalf ? hl2 : hl)[h] = s;
    }
    __syncthreads();

    // ============== Linear 128 -> 1, sigmoid ==============
    if (wid == 0) {
        float v = 0.f;
        #pragma unroll
        for (int i = lane; i < 128; i += 32) {
            float hv = fmaxf(hl[i] + hl2[i], 0.f);
            v += hv * __ldg(lW2 + i);
        }
        #pragma unroll
        for (int o = 16; o; o >>= 1) v += __shfl_xor_sync(0xffffffffu, v, o);
        if (lane == 0)
            out[g] = 1.0f / (1.0f + expf(-(v + __ldg(lb2))));
    }
}

extern "C" void kernel_launch(void* const* d_in, const int* in_sizes, int n_in,
                              void* d_out, int out_size)
{
    const float* x    = (const float*)d_in[0];
    const int*   ei   = (const int*)  d_in[1];
    const float* W1   = (const float*)d_in[3];
    const float* b1   = (const float*)d_in[4];
    const float* W2   = (const float*)d_in[5];
    const float* b2   = (const float*)d_in[6];
    const float* W3   = (const float*)d_in[7];
    const float* b3   = (const float*)d_in[8];
    const float* W4   = (const float*)d_in[9];
    const float* b4   = (const float*)d_in[10];
    const float* cW1  = (const float*)d_in[11];
    const float* cb1  = (const float*)d_in[12];
    const float* cW2  = (const float*)d_in[13];
    const float* cb2  = (const float*)d_in[14];
    const float* lW1  = (const float*)d_in[15];
    const float* lb1  = (const float*)d_in[16];
    const float* lW2  = (const float*)d_in[17];
    const float* lb2  = (const float*)d_in[18];

    const int E = in_sizes[1] / 2;
    const int* esrc = ei;
    const int* edst = ei + E;

    cudaFuncSetAttribute(dgcnn_fused_kernel,
                         cudaFuncAttributeMaxDynamicSharedMemorySize, SM_BYTES);

    dgcnn_fused_kernel<<<BGRAPH, NTHREADS, SM_BYTES>>>(
        x, esrc, edst,
        W1, b1, W2, b2, W3, b3, W4, b4,
        cW1, cb1, cW2, cb2, lW1, lb1, lW2, lb2,
        (float*)d_out);
}